// round 13
// baseline (speedup 1.0000x reference)
#include <cuda_runtime.h>

#define BB    4096
#define TT    50
#define IN_W  4
#define HH    256
#define G4    1024   // 4*H
#define KK    3
#define FSS   6
#define BM    10
#define NP    (BM/2)    // batch pairs per block (5)
#define NTHR  256
#define NBLK  ((BB + BM - 1)/BM)   // 410  (<= 444 = 148 SMs x 3 slots)
#define NPAIR (BB/2)               // 2048 total batch pairs

typedef unsigned long long u64;

// ---------------- device scratch (no allocations allowed) ----------------
__device__ float g_h0[BB*HH], g_c0[BB*HH], g_h1[BB*HH], g_c1[BB*HH];
// packed weights: per matrix [H/4][1024 rows][4 k-values]
__device__ float p_Whh0 [(HH/4)*G4*4];
__device__ float p_Wih1 [(HH/4)*G4*4];
__device__ float p_Whh1 [(HH/4)*G4*4];
__device__ float p_dWhh0[KK*(HH/4)*G4*4];
__device__ float p_dWih1[KK*(HH/4)*G4*4];
__device__ float p_dWhh1[KK*(HH/4)*G4*4];

// ---------------- packed f32x2 helpers ----------------
__device__ __forceinline__ u64 pk2(float lo, float hi){
  u64 r; asm("mov.b64 %0,{%1,%2};" : "=l"(r) : "f"(lo), "f"(hi)); return r;
}
__device__ __forceinline__ void upk2(float &lo, float &hi, u64 v){
  asm("mov.b64 {%0,%1},%2;" : "=f"(lo), "=f"(hi) : "l"(v));
}
__device__ __forceinline__ u64 dup2(float w){ return pk2(w, w); }
__device__ __forceinline__ u64 ffma2(u64 a, u64 b, u64 c){
  u64 d; asm("fma.rn.f32x2 %0,%1,%2,%3;" : "=l"(d) : "l"(a), "l"(b), "l"(c)); return d;
}

__device__ __forceinline__ float sigf(float x){ return 1.0f/(1.0f + __expf(-x)); }
__device__ __forceinline__ float tanh_fast(float x){
  x = fminf(fmaxf(x, -10.0f), 10.0f);
  float e = __expf(2.0f*x);
  return (e - 1.0f)/(e + 1.0f);
}

// gates accumulation (packed): A[g][p] += W[g*H+j][k] * hpair[p][k], k=0..255
// Weights: LDG.128 full-density. h: LDS.128 broadcast.
// unroll 1: 6 warps/SMSP now hide the load latency (reg budget = 84).
__device__ __forceinline__ void accum2(
    u64 (&A)[4][NP], const float* __restrict__ Pf,
    const float2* __restrict__ hsrc, int j)
{
  #pragma unroll 1
  for (int k4 = 0; k4 < HH/4; k4++){
    const float4* wp = (const float4*)(Pf + (size_t)k4*(G4*4)) + j;
    float4 w0 = wp[0];
    float4 w1 = wp[HH];
    float4 w2 = wp[2*HH];
    float4 w3 = wp[3*HH];
    #pragma unroll
    for (int kh = 0; kh < 2; kh++){
      u64 W00 = dup2(kh ? w0.z : w0.x), W01 = dup2(kh ? w0.w : w0.y);
      u64 W10 = dup2(kh ? w1.z : w1.x), W11 = dup2(kh ? w1.w : w1.y);
      u64 W20 = dup2(kh ? w2.z : w2.x), W21 = dup2(kh ? w2.w : w2.y);
      u64 W30 = dup2(kh ? w3.z : w3.x), W31 = dup2(kh ? w3.w : w3.y);
      const float2* hp = hsrc + k4*4 + 2*kh;
      #pragma unroll
      for (int p = 0; p < NP; p++){
        float4 hv = *(const float4*)(hp + p*HH);   // LDS.128 broadcast: k, k+1 pair
        u64 h0 = pk2(hv.x, hv.y);
        u64 h1 = pk2(hv.z, hv.w);
        A[0][p] = ffma2(W00, h0, A[0][p]);
        A[1][p] = ffma2(W10, h0, A[1][p]);
        A[2][p] = ffma2(W20, h0, A[2][p]);
        A[3][p] = ffma2(W30, h0, A[3][p]);
        A[0][p] = ffma2(W01, h1, A[0][p]);
        A[1][p] = ffma2(W11, h1, A[1][p]);
        A[2][p] = ffma2(W21, h1, A[2][p]);
        A[3][p] = ffma2(W31, h1, A[3][p]);
      }
    }
  }
}

__device__ __forceinline__ void cell_update2(
    float2* __restrict__ hs, float2* __restrict__ cs, int j, u64 (&A)[4][NP])
{
  #pragma unroll
  for (int p = 0; p < NP; p++){
    float i0,i1,f0,f1,g0,g1,o0,o1;
    upk2(i0,i1,A[0][p]); upk2(f0,f1,A[1][p]);
    upk2(g0,g1,A[2][p]); upk2(o0,o1,A[3][p]);
    float2 c = cs[p*HH + j];
    c.x = sigf(f0)*c.x + sigf(i0)*tanh_fast(g0);
    c.y = sigf(f1)*c.y + sigf(i1)*tanh_fast(g1);
    cs[p*HH + j] = c;
    float2 h;
    h.x = sigf(o0)*tanh_fast(c.x);
    h.y = sigf(o1)*tanh_fast(c.y);
    hs[p*HH + j] = h;
  }
}

// ---------------- fused weight repack (ONE launch) ----
// W[m][row][k] -> P[m][k/4][row][4]
__global__ void pack_all_kernel(
    const float* __restrict__ s0, const float* __restrict__ s1, const float* __restrict__ s2,
    const float* __restrict__ s3, const float* __restrict__ s4, const float* __restrict__ s5,
    float* __restrict__ d0, float* __restrict__ d1, float* __restrict__ d2,
    float* __restrict__ d3, float* __restrict__ d4, float* __restrict__ d5)
{
  const int ONE = G4*HH;                       // 262144
  int idx = blockIdx.x * blockDim.x + threadIdx.x;
  const float* src; float* dst; int local;
  if (idx < 3*ONE){
    int w = idx / ONE; local = idx % ONE;
    src = (w==0) ? s0 : (w==1 ? s1 : s2);
    dst = (w==0) ? d0 : (w==1 ? d1 : d2);
  } else {
    int r = idx - 3*ONE;
    if (r >= 3*KK*ONE) return;
    int w = r / (KK*ONE); local = r % (KK*ONE);
    src = (w==0) ? s3 : (w==1 ? s4 : s5);
    dst = (w==0) ? d3 : (w==1 ? d4 : d5);
  }
  int m = local / ONE;
  int rr = (local / HH) % G4;
  int k  = local % HH;
  dst[(size_t)m*(HH/4)*G4*4 + (size_t)(k>>2)*G4*4 + rr*4 + (k&3)] = src[local];
}

// ---------------- the fused persistent kernel ----------------
__global__ void __launch_bounds__(NTHR, 3) lstm_fused_kernel(
    const float* __restrict__ x,
    const float* __restrict__ eWih0,
    const float* __restrict__ ebih0, const float* __restrict__ ebhh0,
    const float* __restrict__ ebih1, const float* __restrict__ ebhh1,
    const float* __restrict__ dWih0,
    const float* __restrict__ dbih0, const float* __restrict__ dbhh0,
    const float* __restrict__ dbih1, const float* __restrict__ dbhh1,
    const float* __restrict__ headW, const float* __restrict__ headb,
    const float* __restrict__ confW, const float* __restrict__ confb,
    float* __restrict__ out)
{
  extern __shared__ float sm[];
  float2* hs0    = (float2*)sm;              // NP*HH float2 each
  float2* cs0    = hs0 + NP*HH;
  float2* cs1    = cs0 + NP*HH;
  float2* hs1    = cs1 + NP*HH;
  float*  bias0  = (float*)(hs1 + NP*HH);    // G4 floats
  float2* bias1d = (float2*)(bias0 + G4);    // G4 float2 (dup-packed)
  float*  wis    = (float*)(bias1d + G4);    // G4*4 floats (input weights)
  float*  xin    = wis + G4*IN_W;            // BM*IN_W
  float*  tmp    = xin + BM*IN_W;            // BM*KK

  const int j  = threadIdx.x;                // hidden unit
  const int b0 = blockIdx.x * BM;            // first batch row of this block
  const int p0 = b0 >> 1;                    // first batch pair

  // constants into smem (encoder set)
  #pragma unroll
  for (int g = 0; g < 4; g++){
    bias0[g*HH + j] = ebih0[g*HH + j] + ebhh0[g*HH + j];
    float b1 = ebih1[g*HH + j] + ebhh1[g*HH + j];
    bias1d[g*HH + j] = make_float2(b1, b1);
    float4 w = *(const float4*)(eWih0 + (size_t)(g*HH + j) * IN_W);
    *(float4*)(wis + (g*HH + j)*4) = w;
  }
  // zero state
  #pragma unroll
  for (int p = 0; p < NP; p++){
    hs0[p*HH + j] = make_float2(0.f,0.f); cs0[p*HH + j] = make_float2(0.f,0.f);
    hs1[p*HH + j] = make_float2(0.f,0.f); cs1[p*HH + j] = make_float2(0.f,0.f);
  }
  __syncthreads();

  u64 A[4][NP];

  // ================= encoder: 50 steps =================
  for (int t = 0; t < TT; t++){
    if (j < BM*IN_W){
      int row = b0 + j/IN_W; if (row >= BB) row = BB-1;   // clamp (tail block)
      xin[j] = x[(size_t)row*TT*IN_W + t*IN_W + (j & 3)];
    }
    __syncthreads();

    // layer 0: bias + Wih0 @ x_t
    #pragma unroll
    for (int p = 0; p < NP; p++){
      const float* xe = xin + (2*p)*4;
      const float* xo = xe + 4;
      #pragma unroll
      for (int g = 0; g < 4; g++){
        const float* w = wis + (g*HH + j)*4;
        float bb = bias0[g*HH + j];
        float ve = bb + w[0]*xe[0] + w[1]*xe[1] + w[2]*xe[2] + w[3]*xe[3];
        float vo = bb + w[0]*xo[0] + w[1]*xo[1] + w[2]*xo[2] + w[3]*xo[3];
        A[g][p] = pk2(ve, vo);
      }
    }
    accum2(A, p_Whh0, hs0, j);
    __syncthreads();
    cell_update2(hs0, cs0, j, A);
    __syncthreads();

    // layer 1: bias + Wih1 @ h0 + Whh1 @ h1
    #pragma unroll
    for (int g = 0; g < 4; g++){
      u64 bv = *(const u64*)(bias1d + g*HH + j);
      #pragma unroll
      for (int p = 0; p < NP; p++) A[g][p] = bv;
    }
    accum2(A, p_Wih1, hs0, j);
    accum2(A, p_Whh1, hs1, j);
    __syncthreads();
    cell_update2(hs1, cs1, j, A);
    __syncthreads();
  }

  // save encoder final state (skip out-of-range pairs in the tail block)
  #pragma unroll
  for (int p = 0; p < NP; p++){
    if (p0 + p < NPAIR){
      size_t gi = (size_t)(p0 + p)*HH + j;
      ((float2*)g_h0)[gi] = hs0[p*HH + j];  ((float2*)g_c0)[gi] = cs0[p*HH + j];
      ((float2*)g_h1)[gi] = hs1[p*HH + j];  ((float2*)g_c1)[gi] = cs1[p*HH + j];
    }
  }

  // ================= confidence head (softmax over K) =================
  if (j < BM*KK){
    int b = j / KK, kk = j % KK;
    const float* hrow = (const float*)(hs1 + (b>>1)*HH) + (b & 1);
    float s = confb[kk];
    const float* cw = confW + (size_t)kk*HH;
    for (int u = 0; u < HH; u++) s += hrow[2*u] * cw[u];
    tmp[j] = s;
  }
  __syncthreads();
  if (j < BM && b0 + j < BB){
    float l0 = tmp[j*KK], l1 = tmp[j*KK+1], l2 = tmp[j*KK+2];
    float m  = fmaxf(l0, fmaxf(l1, l2));
    float e0 = __expf(l0-m), e1 = __expf(l1-m), e2 = __expf(l2-m);
    float inv = 1.0f/(e0+e1+e2);
    size_t base = (size_t)BB*KK*FSS*2 + (size_t)(b0 + j)*KK;
    out[base+0] = e0*inv; out[base+1] = e1*inv; out[base+2] = e2*inv;
  }

  // ================= decoder: K modes x FS steps =================
  for (int km = 0; km < KK; km++){
    __syncthreads();
    // reload encoder state (clamped for tail block) + per-mode constants
    #pragma unroll
    for (int p = 0; p < NP; p++){
      int pi = p0 + p; if (pi >= NPAIR) pi = NPAIR-1;     // clamp read
      size_t gi = (size_t)pi*HH + j;
      hs0[p*HH + j] = ((const float2*)g_h0)[gi];  cs0[p*HH + j] = ((const float2*)g_c0)[gi];
      hs1[p*HH + j] = ((const float2*)g_h1)[gi];  cs1[p*HH + j] = ((const float2*)g_c1)[gi];
    }
    #pragma unroll
    for (int g = 0; g < 4; g++){
      bias0[g*HH + j] = dbih0[(size_t)km*G4 + g*HH + j] + dbhh0[(size_t)km*G4 + g*HH + j];
      float b1 = dbih1[(size_t)km*G4 + g*HH + j] + dbhh1[(size_t)km*G4 + g*HH + j];
      bias1d[g*HH + j] = make_float2(b1, b1);
      float2 w = *(const float2*)(dWih0 + ((size_t)km*G4 + g*HH + j) * 2);
      *(float2*)(wis + (g*HH + j)*4) = w;   // reuse wis slots 0,1
    }
    if (j < BM*2){
      int row = b0 + j/2; if (row >= BB) row = BB-1;      // clamp (tail block)
      xin[j] = x[(size_t)row*TT*IN_W + (TT-1)*IN_W + (j & 1)];
    }
    __syncthreads();

    const float* Pd0 = p_dWhh0 + (size_t)km*(HH/4)*G4*4;
    const float* Pi1 = p_dWih1 + (size_t)km*(HH/4)*G4*4;
    const float* Ph1 = p_dWhh1 + (size_t)km*(HH/4)*G4*4;

    for (int s = 0; s < FSS; s++){
      // layer 0
      #pragma unroll
      for (int p = 0; p < NP; p++){
        float e0i = xin[(2*p)*2],   e1i = xin[(2*p)*2+1];
        float o0i = xin[(2*p+1)*2], o1i = xin[(2*p+1)*2+1];
        #pragma unroll
        for (int g = 0; g < 4; g++){
          const float* w = wis + (g*HH + j)*4;
          float bb = bias0[g*HH + j];
          float ve = bb + w[0]*e0i + w[1]*e1i;
          float vo = bb + w[0]*o0i + w[1]*o1i;
          A[g][p] = pk2(ve, vo);
        }
      }
      accum2(A, Pd0, hs0, j);
      __syncthreads();
      cell_update2(hs0, cs0, j, A);
      __syncthreads();

      // layer 1
      #pragma unroll
      for (int g = 0; g < 4; g++){
        u64 bv = *(const u64*)(bias1d + g*HH + j);
        #pragma unroll
        for (int p = 0; p < NP; p++) A[g][p] = bv;
      }
      accum2(A, Pi1, hs0, j);
      accum2(A, Ph1, hs1, j);
      __syncthreads();
      cell_update2(hs1, cs1, j, A);
      __syncthreads();

      // head
      if (j < BM*2){
        int b = j >> 1, o = j & 1;
        const float* hrow = (const float*)(hs1 + (b>>1)*HH) + (b & 1);
        float pacc = headb[(size_t)km*2 + o];
        const float* hw = headW + ((size_t)km*2 + o)*HH;
        for (int u = 0; u < HH; u++) pacc += hrow[2*u] * hw[u];
        if (b0 + b < BB)
          out[(size_t)(b0 + b)*(KK*FSS*2) + km*(FSS*2) + s*2 + o] = pacc;
        xin[b*2 + o] = pacc;  // autoregressive feedback (smem, always ok)
      }
      __syncthreads();
    }
  }
}

// ---------------- launch ----------------
extern "C" void kernel_launch(void* const* d_in, const int* in_sizes, int n_in,
                              void* d_out, int out_size)
{
  const float* x     = (const float*)d_in[0];
  const float* eWih0 = (const float*)d_in[1];
  const float* eWhh0 = (const float*)d_in[2];
  const float* ebih0 = (const float*)d_in[3];
  const float* ebhh0 = (const float*)d_in[4];
  const float* eWih1 = (const float*)d_in[5];
  const float* eWhh1 = (const float*)d_in[6];
  const float* ebih1 = (const float*)d_in[7];
  const float* ebhh1 = (const float*)d_in[8];
  const float* dWih0 = (const float*)d_in[9];
  const float* dWhh0 = (const float*)d_in[10];
  const float* dbih0 = (const float*)d_in[11];
  const float* dbhh0 = (const float*)d_in[12];
  const float* dWih1 = (const float*)d_in[13];
  const float* dWhh1 = (const float*)d_in[14];
  const float* dbih1 = (const float*)d_in[15];
  const float* dbhh1 = (const float*)d_in[16];
  const float* headW = (const float*)d_in[17];
  const float* headb = (const float*)d_in[18];
  const float* confW = (const float*)d_in[19];
  const float* confb = (const float*)d_in[20];
  float* out = (float*)d_out;

  float *pp_Whh0, *pp_Wih1, *pp_Whh1, *pp_dWhh0, *pp_dWih1, *pp_dWhh1;
  cudaGetSymbolAddress((void**)&pp_Whh0,  p_Whh0);
  cudaGetSymbolAddress((void**)&pp_Wih1,  p_Wih1);
  cudaGetSymbolAddress((void**)&pp_Whh1,  p_Whh1);
  cudaGetSymbolAddress((void**)&pp_dWhh0, p_dWhh0);
  cudaGetSymbolAddress((void**)&pp_dWih1, p_dWih1);
  cudaGetSymbolAddress((void**)&pp_dWhh1, p_dWhh1);

  const int PT = 256;
  int total = 3*(G4*HH) + 3*(KK*G4*HH);
  pack_all_kernel<<<(total + PT - 1)/PT, PT>>>(
      eWhh0, eWih1, eWhh1, dWhh0, dWih1, dWhh1,
      pp_Whh0, pp_Wih1, pp_Whh1, pp_dWhh0, pp_dWih1, pp_dWhh1);

  const int SMEM_BYTES = (4*NP*HH*2 + G4 + G4*2 + G4*IN_W + BM*IN_W + BM*KK)
                         * (int)sizeof(float);
  cudaFuncSetAttribute(lstm_fused_kernel,
                       cudaFuncAttributeMaxDynamicSharedMemorySize, SMEM_BYTES);

  lstm_fused_kernel<<<NBLK, NTHR, SMEM_BYTES>>>(
      x, eWih0, ebih0, ebhh0, ebih1, ebhh1,
      dWih0, dbih0, dbhh0, dbih1, dbhh1,
      headW, headb, confW, confb, out);
}

// round 14
// speedup vs baseline: 1.4765x; 1.4765x over previous
#include <cuda_runtime.h>

#define BB    4096
#define TT    50
#define IN_W  4
#define HH    256
#define G4    1024   // 4*H
#define KK    3
#define FSS   6
#define BM    14
#define NP    (BM/2)    // batch pairs per block (7)
#define NTHR  256
#define NBLK  ((BB + BM - 1)/BM)   // 293  (~296 = 148 SMs x 2 slots)
#define NPAIR (BB/2)               // 2048 total batch pairs

typedef unsigned long long u64;

// ---------------- device scratch (no allocations allowed) ----------------
__device__ float g_h0[BB*HH], g_c0[BB*HH], g_h1[BB*HH], g_c1[BB*HH];
// packed weights: per matrix [H/4][1024 rows][4 k-values]
__device__ float p_Whh0 [(HH/4)*G4*4];
__device__ float p_Wih1 [(HH/4)*G4*4];
__device__ float p_Whh1 [(HH/4)*G4*4];
__device__ float p_dWhh0[KK*(HH/4)*G4*4];
__device__ float p_dWih1[KK*(HH/4)*G4*4];
__device__ float p_dWhh1[KK*(HH/4)*G4*4];

// ---------------- packed f32x2 helpers ----------------
__device__ __forceinline__ u64 pk2(float lo, float hi){
  u64 r; asm("mov.b64 %0,{%1,%2};" : "=l"(r) : "f"(lo), "f"(hi)); return r;
}
__device__ __forceinline__ void upk2(float &lo, float &hi, u64 v){
  asm("mov.b64 {%0,%1},%2;" : "=f"(lo), "=f"(hi) : "l"(v));
}
__device__ __forceinline__ u64 dup2(float w){ return pk2(w, w); }
__device__ __forceinline__ u64 ffma2(u64 a, u64 b, u64 c){
  u64 d; asm("fma.rn.f32x2 %0,%1,%2,%3;" : "=l"(d) : "l"(a), "l"(b), "l"(c)); return d;
}

__device__ __forceinline__ float sigf(float x){ return 1.0f/(1.0f + __expf(-x)); }
__device__ __forceinline__ float tanh_fast(float x){
  x = fminf(fmaxf(x, -10.0f), 10.0f);
  float e = __expf(2.0f*x);
  return (e - 1.0f)/(e + 1.0f);
}

// gates accumulation with cp.async weight staging.
// Each thread stages its OWN 4x16B weight slice per k4 into thread-private,
// double-buffered SMEM (no cross-thread sharing -> no barriers).
// Pipeline distance 2: wait_group 1 at top guarantees this k4's copy landed.
// WAR on buffer reuse is safe: consuming FFMA2s issue before the refill
// cp.async in program order (scoreboard forces LDS data delivery first).
__device__ __forceinline__ void accum2(
    u64 (&A)[4][NP], const float* __restrict__ Pf,
    const float2* __restrict__ hsrc, int j, unsigned wb)
{
  // prologue: prefetch k4 = 0, 1
  #pragma unroll
  for (int pb = 0; pb < 2; pb++){
    const float* src = Pf + (size_t)pb*(G4*4) + j*4;
    #pragma unroll
    for (int g = 0; g < 4; g++){
      asm volatile("cp.async.cg.shared.global [%0], [%1], 16;\n"
        :: "r"(wb + pb*2048u + g*512u), "l"(src + g*HH*4) : "memory");
    }
    asm volatile("cp.async.commit_group;\n" ::: "memory");
  }

  #pragma unroll 1
  for (int k4 = 0; k4 < HH/4; k4++){
    asm volatile("cp.async.wait_group 1;\n" ::: "memory");
    unsigned rb = wb + (unsigned)(k4 & 1)*2048u;
    float4 w0, w1, w2, w3;
    asm volatile("ld.shared.v4.f32 {%0,%1,%2,%3}, [%4];"
      : "=f"(w0.x),"=f"(w0.y),"=f"(w0.z),"=f"(w0.w) : "r"(rb));
    asm volatile("ld.shared.v4.f32 {%0,%1,%2,%3}, [%4];"
      : "=f"(w1.x),"=f"(w1.y),"=f"(w1.z),"=f"(w1.w) : "r"(rb + 512u));
    asm volatile("ld.shared.v4.f32 {%0,%1,%2,%3}, [%4];"
      : "=f"(w2.x),"=f"(w2.y),"=f"(w2.z),"=f"(w2.w) : "r"(rb + 1024u));
    asm volatile("ld.shared.v4.f32 {%0,%1,%2,%3}, [%4];"
      : "=f"(w3.x),"=f"(w3.y),"=f"(w3.z),"=f"(w3.w) : "r"(rb + 1536u));

    #pragma unroll
    for (int kh = 0; kh < 2; kh++){
      u64 W00 = dup2(kh ? w0.z : w0.x), W01 = dup2(kh ? w0.w : w0.y);
      u64 W10 = dup2(kh ? w1.z : w1.x), W11 = dup2(kh ? w1.w : w1.y);
      u64 W20 = dup2(kh ? w2.z : w2.x), W21 = dup2(kh ? w2.w : w2.y);
      u64 W30 = dup2(kh ? w3.z : w3.x), W31 = dup2(kh ? w3.w : w3.y);
      const float2* hp = hsrc + k4*4 + 2*kh;
      #pragma unroll
      for (int p = 0; p < NP; p++){
        float4 hv = *(const float4*)(hp + p*HH);   // LDS.128 broadcast: k, k+1 pair
        u64 h0 = pk2(hv.x, hv.y);
        u64 h1 = pk2(hv.z, hv.w);
        A[0][p] = ffma2(W00, h0, A[0][p]);
        A[1][p] = ffma2(W10, h0, A[1][p]);
        A[2][p] = ffma2(W20, h0, A[2][p]);
        A[3][p] = ffma2(W30, h0, A[3][p]);
        A[0][p] = ffma2(W01, h1, A[0][p]);
        A[1][p] = ffma2(W11, h1, A[1][p]);
        A[2][p] = ffma2(W21, h1, A[2][p]);
        A[3][p] = ffma2(W31, h1, A[3][p]);
      }
    }

    // refill the just-consumed buffer with k4+2 (clamped re-fetch near the end)
    int nk = (k4 + 2 < HH/4) ? (k4 + 2) : (HH/4 - 1);
    const float* nsrc = Pf + (size_t)nk*(G4*4) + j*4;
    #pragma unroll
    for (int g = 0; g < 4; g++){
      asm volatile("cp.async.cg.shared.global [%0], [%1], 16;\n"
        :: "r"(rb + g*512u), "l"(nsrc + g*HH*4) : "memory");
    }
    asm volatile("cp.async.commit_group;\n" ::: "memory");
  }
  asm volatile("cp.async.wait_group 0;\n" ::: "memory");   // drain before next use
}

__device__ __forceinline__ void cell_update2(
    float2* __restrict__ hs, float2* __restrict__ cs, int j, u64 (&A)[4][NP])
{
  #pragma unroll
  for (int p = 0; p < NP; p++){
    float i0,i1,f0,f1,g0,g1,o0,o1;
    upk2(i0,i1,A[0][p]); upk2(f0,f1,A[1][p]);
    upk2(g0,g1,A[2][p]); upk2(o0,o1,A[3][p]);
    float2 c = cs[p*HH + j];
    c.x = sigf(f0)*c.x + sigf(i0)*tanh_fast(g0);
    c.y = sigf(f1)*c.y + sigf(i1)*tanh_fast(g1);
    cs[p*HH + j] = c;
    float2 h;
    h.x = sigf(o0)*tanh_fast(c.x);
    h.y = sigf(o1)*tanh_fast(c.y);
    hs[p*HH + j] = h;
  }
}

// ---------------- fused weight repack (ONE launch) ----
// W[m][row][k] -> P[m][k/4][row][4]
__global__ void pack_all_kernel(
    const float* __restrict__ s0, const float* __restrict__ s1, const float* __restrict__ s2,
    const float* __restrict__ s3, const float* __restrict__ s4, const float* __restrict__ s5,
    float* __restrict__ d0, float* __restrict__ d1, float* __restrict__ d2,
    float* __restrict__ d3, float* __restrict__ d4, float* __restrict__ d5)
{
  const int ONE = G4*HH;                       // 262144
  int idx = blockIdx.x * blockDim.x + threadIdx.x;
  const float* src; float* dst; int local;
  if (idx < 3*ONE){
    int w = idx / ONE; local = idx % ONE;
    src = (w==0) ? s0 : (w==1 ? s1 : s2);
    dst = (w==0) ? d0 : (w==1 ? d1 : d2);
  } else {
    int r = idx - 3*ONE;
    if (r >= 3*KK*ONE) return;
    int w = r / (KK*ONE); local = r % (KK*ONE);
    src = (w==0) ? s3 : (w==1 ? s4 : s5);
    dst = (w==0) ? d3 : (w==1 ? d4 : d5);
  }
  int m = local / ONE;
  int rr = (local / HH) % G4;
  int k  = local % HH;
  dst[(size_t)m*(HH/4)*G4*4 + (size_t)(k>>2)*G4*4 + rr*4 + (k&3)] = src[local];
}

// ---------------- the fused persistent kernel ----------------
__global__ void __launch_bounds__(NTHR, 2) lstm_fused_kernel(
    const float* __restrict__ x,
    const float* __restrict__ eWih0,
    const float* __restrict__ ebih0, const float* __restrict__ ebhh0,
    const float* __restrict__ ebih1, const float* __restrict__ ebhh1,
    const float* __restrict__ dWih0,
    const float* __restrict__ dbih0, const float* __restrict__ dbhh0,
    const float* __restrict__ dbih1, const float* __restrict__ dbhh1,
    const float* __restrict__ headW, const float* __restrict__ headb,
    const float* __restrict__ confW, const float* __restrict__ confb,
    float* __restrict__ out)
{
  extern __shared__ float sm[];
  float*  wbuf   = sm;                       // 8 warps * 2 bufs * 4 gates * 512B = 32KB
  float2* hs0    = (float2*)(wbuf + 8192);   // NP*HH float2 each
  float2* cs0    = hs0 + NP*HH;
  float2* cs1    = cs0 + NP*HH;
  float2* hs1    = cs1 + NP*HH;
  float*  bias0  = (float*)(hs1 + NP*HH);    // G4 floats
  float2* bias1d = (float2*)(bias0 + G4);    // G4 float2 (dup-packed)
  float*  xin    = (float*)(bias1d + G4);    // BM*IN_W
  float*  tmp    = xin + BM*IN_W;            // BM*KK

  const int j  = threadIdx.x;                // hidden unit
  const int b0 = blockIdx.x * BM;            // first batch row of this block
  const int p0 = b0 >> 1;                    // first batch pair

  // thread-private cp.async slot: [warp][buf(2)][gate(4)][lane]
  const unsigned wb = (unsigned)__cvta_generic_to_shared(wbuf)
                    + (unsigned)(j >> 5)*4096u + (unsigned)(j & 31)*16u;

  // constants into smem / regs (encoder set)
  float4 wi0[4];
  #pragma unroll
  for (int g = 0; g < 4; g++){
    bias0[g*HH + j] = ebih0[g*HH + j] + ebhh0[g*HH + j];
    float b1 = ebih1[g*HH + j] + ebhh1[g*HH + j];
    bias1d[g*HH + j] = make_float2(b1, b1);
    wi0[g] = *(const float4*)(eWih0 + (size_t)(g*HH + j) * IN_W);
  }
  // zero state
  #pragma unroll
  for (int p = 0; p < NP; p++){
    hs0[p*HH + j] = make_float2(0.f,0.f); cs0[p*HH + j] = make_float2(0.f,0.f);
    hs1[p*HH + j] = make_float2(0.f,0.f); cs1[p*HH + j] = make_float2(0.f,0.f);
  }
  __syncthreads();

  u64 A[4][NP];

  // ================= encoder: 50 steps =================
  for (int t = 0; t < TT; t++){
    if (j < BM*IN_W){
      int row = b0 + j/IN_W; if (row >= BB) row = BB-1;   // clamp (tail block)
      xin[j] = x[(size_t)row*TT*IN_W + t*IN_W + (j & 3)];
    }
    __syncthreads();

    // layer 0: bias + Wih0 @ x_t
    #pragma unroll
    for (int p = 0; p < NP; p++){
      const float* xe = xin + (2*p)*4;
      const float* xo = xe + 4;
      #pragma unroll
      for (int g = 0; g < 4; g++){
        float bb = bias0[g*HH + j];
        float ve = bb + wi0[g].x*xe[0] + wi0[g].y*xe[1] + wi0[g].z*xe[2] + wi0[g].w*xe[3];
        float vo = bb + wi0[g].x*xo[0] + wi0[g].y*xo[1] + wi0[g].z*xo[2] + wi0[g].w*xo[3];
        A[g][p] = pk2(ve, vo);
      }
    }
    accum2(A, p_Whh0, hs0, j, wb);
    __syncthreads();
    cell_update2(hs0, cs0, j, A);
    __syncthreads();

    // layer 1: bias + Wih1 @ h0 + Whh1 @ h1
    #pragma unroll
    for (int g = 0; g < 4; g++){
      u64 bv = *(const u64*)(bias1d + g*HH + j);
      #pragma unroll
      for (int p = 0; p < NP; p++) A[g][p] = bv;
    }
    accum2(A, p_Wih1, hs0, j, wb);
    accum2(A, p_Whh1, hs1, j, wb);
    __syncthreads();
    cell_update2(hs1, cs1, j, A);
    __syncthreads();
  }

  // save encoder final state (skip out-of-range pairs in the tail block)
  #pragma unroll
  for (int p = 0; p < NP; p++){
    if (p0 + p < NPAIR){
      size_t gi = (size_t)(p0 + p)*HH + j;
      ((float2*)g_h0)[gi] = hs0[p*HH + j];  ((float2*)g_c0)[gi] = cs0[p*HH + j];
      ((float2*)g_h1)[gi] = hs1[p*HH + j];  ((float2*)g_c1)[gi] = cs1[p*HH + j];
    }
  }

  // ================= confidence head (softmax over K) =================
  if (j < BM*KK){
    int b = j / KK, kk = j % KK;
    const float* hrow = (const float*)(hs1 + (b>>1)*HH) + (b & 1);
    float s = confb[kk];
    const float* cw = confW + (size_t)kk*HH;
    for (int u = 0; u < HH; u++) s += hrow[2*u] * cw[u];
    tmp[j] = s;
  }
  __syncthreads();
  if (j < BM && b0 + j < BB){
    float l0 = tmp[j*KK], l1 = tmp[j*KK+1], l2 = tmp[j*KK+2];
    float m  = fmaxf(l0, fmaxf(l1, l2));
    float e0 = __expf(l0-m), e1 = __expf(l1-m), e2 = __expf(l2-m);
    float inv = 1.0f/(e0+e1+e2);
    size_t base = (size_t)BB*KK*FSS*2 + (size_t)(b0 + j)*KK;
    out[base+0] = e0*inv; out[base+1] = e1*inv; out[base+2] = e2*inv;
  }

  // ================= decoder: K modes x FS steps =================
  for (int km = 0; km < KK; km++){
    __syncthreads();
    // reload encoder state (clamped for tail block) + per-mode constants
    #pragma unroll
    for (int p = 0; p < NP; p++){
      int pi = p0 + p; if (pi >= NPAIR) pi = NPAIR-1;     // clamp read
      size_t gi = (size_t)pi*HH + j;
      hs0[p*HH + j] = ((const float2*)g_h0)[gi];  cs0[p*HH + j] = ((const float2*)g_c0)[gi];
      hs1[p*HH + j] = ((const float2*)g_h1)[gi];  cs1[p*HH + j] = ((const float2*)g_c1)[gi];
    }
    float2 dwi[4];
    #pragma unroll
    for (int g = 0; g < 4; g++){
      bias0[g*HH + j] = dbih0[(size_t)km*G4 + g*HH + j] + dbhh0[(size_t)km*G4 + g*HH + j];
      float b1 = dbih1[(size_t)km*G4 + g*HH + j] + dbhh1[(size_t)km*G4 + g*HH + j];
      bias1d[g*HH + j] = make_float2(b1, b1);
      dwi[g] = *(const float2*)(dWih0 + ((size_t)km*G4 + g*HH + j) * 2);
    }
    if (j < BM*2){
      int row = b0 + j/2; if (row >= BB) row = BB-1;      // clamp (tail block)
      xin[j] = x[(size_t)row*TT*IN_W + (TT-1)*IN_W + (j & 1)];
    }
    __syncthreads();

    const float* Pd0 = p_dWhh0 + (size_t)km*(HH/4)*G4*4;
    const float* Pi1 = p_dWih1 + (size_t)km*(HH/4)*G4*4;
    const float* Ph1 = p_dWhh1 + (size_t)km*(HH/4)*G4*4;

    for (int s = 0; s < FSS; s++){
      // layer 0
      #pragma unroll
      for (int p = 0; p < NP; p++){
        float e0i = xin[(2*p)*2],   e1i = xin[(2*p)*2+1];
        float o0i = xin[(2*p+1)*2], o1i = xin[(2*p+1)*2+1];
        #pragma unroll
        for (int g = 0; g < 4; g++){
          float bb = bias0[g*HH + j];
          float ve = bb + dwi[g].x*e0i + dwi[g].y*e1i;
          float vo = bb + dwi[g].x*o0i + dwi[g].y*o1i;
          A[g][p] = pk2(ve, vo);
        }
      }
      accum2(A, Pd0, hs0, j, wb);
      __syncthreads();
      cell_update2(hs0, cs0, j, A);
      __syncthreads();

      // layer 1
      #pragma unroll
      for (int g = 0; g < 4; g++){
        u64 bv = *(const u64*)(bias1d + g*HH + j);
        #pragma unroll
        for (int p = 0; p < NP; p++) A[g][p] = bv;
      }
      accum2(A, Pi1, hs0, j, wb);
      accum2(A, Ph1, hs1, j, wb);
      __syncthreads();
      cell_update2(hs1, cs1, j, A);
      __syncthreads();

      // head
      if (j < BM*2){
        int b = j >> 1, o = j & 1;
        const float* hrow = (const float*)(hs1 + (b>>1)*HH) + (b & 1);
        float pacc = headb[(size_t)km*2 + o];
        const float* hw = headW + ((size_t)km*2 + o)*HH;
        for (int u = 0; u < HH; u++) pacc += hrow[2*u] * hw[u];
        if (b0 + b < BB)
          out[(size_t)(b0 + b)*(KK*FSS*2) + km*(FSS*2) + s*2 + o] = pacc;
        xin[b*2 + o] = pacc;  // autoregressive feedback (smem, always ok)
      }
      __syncthreads();
    }
  }
}

// ---------------- launch ----------------
extern "C" void kernel_launch(void* const* d_in, const int* in_sizes, int n_in,
                              void* d_out, int out_size)
{
  const float* x     = (const float*)d_in[0];
  const float* eWih0 = (const float*)d_in[1];
  const float* eWhh0 = (const float*)d_in[2];
  const float* ebih0 = (const float*)d_in[3];
  const float* ebhh0 = (const float*)d_in[4];
  const float* eWih1 = (const float*)d_in[5];
  const float* eWhh1 = (const float*)d_in[6];
  const float* ebih1 = (const float*)d_in[7];
  const float* ebhh1 = (const float*)d_in[8];
  const float* dWih0 = (const float*)d_in[9];
  const float* dWhh0 = (const float*)d_in[10];
  const float* dbih0 = (const float*)d_in[11];
  const float* dbhh0 = (const float*)d_in[12];
  const float* dWih1 = (const float*)d_in[13];
  const float* dWhh1 = (const float*)d_in[14];
  const float* dbih1 = (const float*)d_in[15];
  const float* dbhh1 = (const float*)d_in[16];
  const float* headW = (const float*)d_in[17];
  const float* headb = (const float*)d_in[18];
  const float* confW = (const float*)d_in[19];
  const float* confb = (const float*)d_in[20];
  float* out = (float*)d_out;

  float *pp_Whh0, *pp_Wih1, *pp_Whh1, *pp_dWhh0, *pp_dWih1, *pp_dWhh1;
  cudaGetSymbolAddress((void**)&pp_Whh0,  p_Whh0);
  cudaGetSymbolAddress((void**)&pp_Wih1,  p_Wih1);
  cudaGetSymbolAddress((void**)&pp_Whh1,  p_Whh1);
  cudaGetSymbolAddress((void**)&pp_dWhh0, p_dWhh0);
  cudaGetSymbolAddress((void**)&pp_dWih1, p_dWih1);
  cudaGetSymbolAddress((void**)&pp_dWhh1, p_dWhh1);

  const int PT = 256;
  int total = 3*(G4*HH) + 3*(KK*G4*HH);
  pack_all_kernel<<<(total + PT - 1)/PT, PT>>>(
      eWhh0, eWih1, eWhh1, dWhh0, dWih1, dWhh1,
      pp_Whh0, pp_Wih1, pp_Whh1, pp_dWhh0, pp_dWih1, pp_dWhh1);

  const int SMEM_BYTES = (8192            // wbuf (32KB)
                        + 4*NP*HH*2       // state
                        + G4              // bias0
                        + G4*2            // bias1d
                        + BM*IN_W + BM*KK)
                         * (int)sizeof(float);
  cudaFuncSetAttribute(lstm_fused_kernel,
                       cudaFuncAttributeMaxDynamicSharedMemorySize, SMEM_BYTES);

  lstm_fused_kernel<<<NBLK, NTHR, SMEM_BYTES>>>(
      x, eWih0, ebih0, ebhh0, ebih1, ebhh1,
      dWih0, dbih0, dbhh0, dbih1, dbhh1,
      headW, headb, confW, confb, out);
}